// round 10
// baseline (speedup 1.0000x reference)
#include <cuda_runtime.h>
#include <cuda_fp16.h>
#include <mma.h>
#include <cstdint>

using namespace nvcuda;

#define NN 100000
#define NE 600000
#define C 128
#define OC 64
#define NREL 3
#define HLD 136   // fp16 tile stride (halves)
#define FLD 132   // f32 tile stride (floats)

// ---------------- scratch (static device globals) ---------------------------
__device__ float  g_agg[(size_t)NREL * NN * C];
__device__ float  g_cnt[NREL * NN];
__device__ __half g_xh[(size_t)NN * C];        // fp16 x
__device__ __half g_th[(size_t)NN * OC];       // fp16 t (pre-aggregation)
__device__ float  g_aggF[(size_t)NN * OC];
__device__ float  g_po[(size_t)NN * OC];
__device__ __half g_Whl[NREL * C * C];         // Wl fp16
__device__ __half g_Whr[NREL * C * C];         // Wr fp16
__device__ __half g_Whf[C * C];                // [Wlf | Wrf] fp16 [k][n]
__device__ float  g_bias_rep[NREL * 16 * C];   // bl replicated over 16 rows
__device__ float  g_bias_rep_f[16 * C];        // [0|blf] replicated over 16 rows

__device__ __forceinline__ uint32_t h2u(__half2 h) {
    return *reinterpret_cast<uint32_t*>(&h);
}
__device__ __forceinline__ void red_add_v4(float* p, float4 v) {
    asm volatile("red.global.add.v4.f32 [%0], {%1, %2, %3, %4};"
                 :: "l"(p), "f"(v.x), "f"(v.y), "f"(v.z), "f"(v.w) : "memory");
}
__device__ __forceinline__ uint32_t smem_u32(const void* p) {
    uint32_t a;
    asm("{ .reg .u64 t; cvta.to.shared.u64 t, %1; cvt.u32.u64 %0, t; }"
        : "=r"(a) : "l"(p));
    return a;
}
__device__ __forceinline__ void cpa16(uint32_t dst, const void* src) {
    asm volatile("cp.async.ca.shared.global [%0], [%1], 16;"
                 :: "r"(dst), "l"(src) : "memory");
}
__device__ __forceinline__ void cpa16z(uint32_t dst, const void* src, bool ok) {
    int sz = ok ? 16 : 0;
    asm volatile("cp.async.ca.shared.global [%0], [%1], 16, %2;"
                 :: "r"(dst), "l"(src), "r"(sz) : "memory");
}
#define CPA_COMMIT() asm volatile("cp.async.commit_group;" ::: "memory")
#define CPA_WAIT0()  asm volatile("cp.async.wait_group 0;" ::: "memory")

// ---------------- kernel P: biases + fp16 weights ---------------------------
__global__ void k_prep(const float* __restrict__ Wl, const float* __restrict__ Wr,
                       const float* __restrict__ Wlf, const float* __restrict__ Wrf,
                       const float* __restrict__ bl, const float* __restrict__ blf) {
    int i0 = blockIdx.x * blockDim.x + threadIdx.x;
    int stride = gridDim.x * blockDim.x;
    for (int i = i0; i < NREL * C * C; i += stride) {
        g_Whl[i] = __float2half(Wl[i]);
        g_Whr[i] = __float2half(Wr[i]);
    }
    for (int i = i0; i < C * C; i += stride) {
        int n = i & (C - 1), k = i >> 7;
        float v = (n < OC) ? Wlf[k * OC + n] : Wrf[k * OC + (n - OC)];
        g_Whf[i] = __float2half(v);
    }
    for (int i = i0; i < NREL * 16 * C; i += stride) {
        int r = i / (16 * C);
        int col = i & (C - 1);
        g_bias_rep[i] = bl[r * C + col];
    }
    for (int i = i0; i < 16 * C; i += stride) {
        int col = i & (C - 1);
        g_bias_rep_f[i] = (col < OC) ? 0.f : blf[col - OC];
    }
}

// ---------------- kernel X: x -> fp16 ---------------------------------------
__global__ void k_xh(const float* __restrict__ x) {
    int i0 = blockIdx.x * blockDim.x + threadIdx.x;
    int stride = gridDim.x * blockDim.x;
    int n8 = NN * C / 8;
    for (int i = i0; i < n8; i += stride) {
        float4 a = *reinterpret_cast<const float4*>(x + (size_t)i * 8);
        float4 b = *reinterpret_cast<const float4*>(x + (size_t)i * 8 + 4);
        uint4 o;
        o.x = h2u(__floats2half2_rn(a.x, a.y));
        o.y = h2u(__floats2half2_rn(a.z, a.w));
        o.z = h2u(__floats2half2_rn(b.x, b.y));
        o.w = h2u(__floats2half2_rn(b.z, b.w));
        *reinterpret_cast<uint4*>(g_xh + (size_t)i * 8) = o;
    }
}

// ---------------- kernel 1: scatter xh, half-warp per edge, MLP-4 -----------
__global__ void k_scatter_x(const int* __restrict__ ei0,
                            const int* __restrict__ ei1,
                            const int* __restrict__ ei2) {
    int r = blockIdx.y;
    const int* ei = (r == 0) ? ei0 : (r == 1) ? ei1 : ei2;
    int gw = (blockIdx.x * blockDim.x + threadIdx.x) >> 5;
    int lane = threadIdx.x & 31;
    int sub = lane >> 4;     // half-warp
    int sl  = lane & 15;     // covers 8 halves (16B) of the 128-col row
    int e0 = (gw * 2 + sub) * 4;
    if (e0 >= NE) return;
    int s[4], d[4];
    bool ok[4];
#pragma unroll
    for (int e = 0; e < 4; e++) {
        s[e] = ei[e0 + e];
        d[e] = ei[NE + e0 + e];
        ok[e] = ((unsigned)s[e] < NN) && ((unsigned)d[e] < NN);
    }
    uint4 hv[4];
#pragma unroll
    for (int e = 0; e < 4; e++)
        if (ok[e])
            hv[e] = *reinterpret_cast<const uint4*>(g_xh + (size_t)s[e] * C + sl * 8);
#pragma unroll
    for (int e = 0; e < 4; e++)
        if (ok[e]) {
            float2 f0 = __half22float2(*reinterpret_cast<__half2*>(&hv[e].x));
            float2 f1 = __half22float2(*reinterpret_cast<__half2*>(&hv[e].y));
            float2 f2 = __half22float2(*reinterpret_cast<__half2*>(&hv[e].z));
            float2 f3 = __half22float2(*reinterpret_cast<__half2*>(&hv[e].w));
            float* a = g_agg + (size_t)r * NN * C + (size_t)d[e] * C + sl * 8;
            red_add_v4(a,     make_float4(f0.x, f0.y, f1.x, f1.y));
            red_add_v4(a + 4, make_float4(f2.x, f2.y, f3.x, f3.y));
        }
    if (sl < 4 && ok[sl])
        atomicAdd(&g_cnt[r * NN + d[sl]], 1.f);
}

// ---------------- fused fp16 WMMA GEMM kernel (512 thr, 16 warps 4x4) -------
__global__ __launch_bounds__(512, 1)
void k_gemm_fused() {
    extern __shared__ char smraw[];
    __half* X_s  = reinterpret_cast<__half*>(smraw);
    __half* A_s  = X_s + 128 * HLD;
    __half* Wl_s = A_s + 128 * HLD;
    __half* Wr_s = Wl_s + 128 * HLD;
    float*  H32  = reinterpret_cast<float*>(smraw);              // over X+A
    __half* Hh   = Wl_s;
    __half* Wf_s = Wr_s;
    float*  Df   = reinterpret_cast<float*>(smraw);              // over X+A

    uint32_t base = smem_u32(smraw);
    uint32_t xa  = base;
    uint32_t wla = base + 2 * 128 * HLD * 2;
    uint32_t wra = wla + 128 * HLD * 2;

    int tid  = threadIdx.x;
    int wid  = tid >> 5;
    int node0 = blockIdx.x * 128;
    int wm = (wid >> 2) * 32;
    int wn = (wid & 3) * 32;

    // X tile via cp.async from g_xh (zero-fill OOB rows)
    for (int it = tid; it < 128 * 16; it += 512) {
        int row = it >> 4, c = it & 15;
        int node = node0 + row;
        bool ok = node < NN;
        const __half* src = g_xh + (size_t)(ok ? node : 0) * C + c * 8;
        cpa16z(xa + row * (HLD * 2) + c * 16, src, ok);
    }

    wmma::fragment<wmma::accumulator, 16, 16, 16, float> hfrag[2][2];
#pragma unroll
    for (int i = 0; i < 2; i++)
#pragma unroll
        for (int j = 0; j < 2; j++) wmma::fill_fragment(hfrag[i][j], 0.f);
    const float inv3 = 1.f / 3.f;

    for (int r = 0; r < NREL; r++) {
        __syncthreads();  // prev MMAs done reading A_s/W tiles
        // W tiles via cp.async (fp16 pre-converted)
        {
            const __half* wl = g_Whl + (size_t)r * C * C;
            const __half* wr = g_Whr + (size_t)r * C * C;
            for (int it = tid; it < 128 * 16; it += 512) {
                int kk = it >> 4, c = it & 15;
                cpa16(wla + kk * (HLD * 2) + c * 16, wl + kk * C + c * 8);
                cpa16(wra + kk * (HLD * 2) + c * 16, wr + kk * C + c * 8);
            }
            CPA_COMMIT();
        }
        // A tile: sync f32 loads + convert (atomic-written source must be f32)
        {
            const float* aggr = g_agg + (size_t)r * NN * C;
            const float* cntr = g_cnt + r * NN;
            for (int it = tid; it < 128 * 32; it += 512) {
                int row = it >> 5, c4 = it & 31;
                int node = node0 + row;
                float4 v = make_float4(0.f, 0.f, 0.f, 0.f);
                if (node < NN) {
                    float inv = 1.f / fmaxf(cntr[node], 1.f);
                    float4 a = *reinterpret_cast<const float4*>(
                        aggr + (size_t)node * C + c4 * 4);
                    v.x = a.x * inv; v.y = a.y * inv;
                    v.z = a.z * inv; v.w = a.w * inv;
                }
                __half2* dp = reinterpret_cast<__half2*>(A_s + row * HLD + c4 * 4);
                dp[0] = __floats2half2_rn(v.x, v.y);
                dp[1] = __floats2half2_rn(v.z, v.w);
            }
        }

        wmma::fragment<wmma::accumulator, 16, 16, 16, float> acc[2][2];
#pragma unroll
        for (int i = 0; i < 2; i++)
#pragma unroll
            for (int j = 0; j < 2; j++)
                wmma::load_matrix_sync(acc[i][j],
                    g_bias_rep + r * 16 * C + wn + j * 16, C, wmma::mem_row_major);

        CPA_WAIT0();
        __syncthreads();

#pragma unroll
        for (int ks = 0; ks < 8; ks++) {
            int k = ks * 16;
            wmma::fragment<wmma::matrix_a, 16, 16, 16, __half,
                           wmma::row_major> af[2], xf[2];
            wmma::fragment<wmma::matrix_b, 16, 16, 16, __half,
                           wmma::row_major> lf[2], rf[2];
#pragma unroll
            for (int i = 0; i < 2; i++) {
                wmma::load_matrix_sync(af[i], A_s + (wm + i * 16) * HLD + k, HLD);
                wmma::load_matrix_sync(xf[i], X_s + (wm + i * 16) * HLD + k, HLD);
            }
#pragma unroll
            for (int j = 0; j < 2; j++) {
                wmma::load_matrix_sync(lf[j], Wl_s + k * HLD + wn + j * 16, HLD);
                wmma::load_matrix_sync(rf[j], Wr_s + k * HLD + wn + j * 16, HLD);
            }
#pragma unroll
            for (int i = 0; i < 2; i++)
#pragma unroll
                for (int j = 0; j < 2; j++) {
                    wmma::mma_sync(acc[i][j], af[i], lf[j], acc[i][j]);
                    wmma::mma_sync(acc[i][j], xf[i], rf[j], acc[i][j]);
                }
        }

#pragma unroll
        for (int i = 0; i < 2; i++)
#pragma unroll
            for (int j = 0; j < 2; j++)
#pragma unroll
                for (int t = 0; t < hfrag[i][j].num_elements; t++)
                    hfrag[i][j].x[t] += fmaxf(acc[i][j].x[t], 0.f) * inv3;
    }

    // ---------------- final GEMM: D_f = h @ [Wlf | Wrf] ---------------------
    __syncthreads();  // MMAs done reading X_s/A_s/W
#pragma unroll
    for (int i = 0; i < 2; i++)
#pragma unroll
        for (int j = 0; j < 2; j++)
            wmma::store_matrix_sync(H32 + (wm + i * 16) * FLD + wn + j * 16,
                                    hfrag[i][j], FLD, wmma::mem_row_major);
    __syncthreads();
    // Wf via cp.async (over Wr_s); convert H32 -> Hh (over Wl_s)
    for (int it = tid; it < 128 * 16; it += 512) {
        int kk = it >> 4, c = it & 15;
        cpa16(wra + kk * (HLD * 2) + c * 16, g_Whf + kk * C + c * 8);
    }
    CPA_COMMIT();
    for (int it = tid; it < 128 * 64; it += 512) {
        int row = it >> 6, c2 = it & 63;
        float2 v = *reinterpret_cast<const float2*>(H32 + row * FLD + c2 * 2);
        *reinterpret_cast<__half2*>(Hh + row * HLD + c2 * 2) =
            __floats2half2_rn(v.x, v.y);
    }
    CPA_WAIT0();
    __syncthreads();

    {
        wmma::fragment<wmma::accumulator, 16, 16, 16, float> acc2[2][2];
#pragma unroll
        for (int i = 0; i < 2; i++)
#pragma unroll
            for (int j = 0; j < 2; j++)
                wmma::load_matrix_sync(acc2[i][j],
                    g_bias_rep_f + wn + j * 16, C, wmma::mem_row_major);

#pragma unroll
        for (int ks = 0; ks < 8; ks++) {
            int k = ks * 16;
            wmma::fragment<wmma::matrix_a, 16, 16, 16, __half,
                           wmma::row_major> hf[2];
            wmma::fragment<wmma::matrix_b, 16, 16, 16, __half,
                           wmma::row_major> wf[2];
#pragma unroll
            for (int i = 0; i < 2; i++)
                wmma::load_matrix_sync(hf[i], Hh + (wm + i * 16) * HLD + k, HLD);
#pragma unroll
            for (int j = 0; j < 2; j++)
                wmma::load_matrix_sync(wf[j], Wf_s + k * HLD + wn + j * 16, HLD);
#pragma unroll
            for (int i = 0; i < 2; i++)
#pragma unroll
                for (int j = 0; j < 2; j++)
                    wmma::mma_sync(acc2[i][j], hf[i], wf[j], acc2[i][j]);
        }
        __syncthreads();  // all warps done reading Hh/Wf (and H32 region)
#pragma unroll
        for (int i = 0; i < 2; i++)
#pragma unroll
            for (int j = 0; j < 2; j++)
                wmma::store_matrix_sync(Df + (wm + i * 16) * FLD + wn + j * 16,
                                        acc2[i][j], FLD, wmma::mem_row_major);
        __syncthreads();
    }

    // epilogue: t (fp16, cols 0..63), po (f32, cols 64..127); zero aggF slice
    {
        int row = tid >> 2;
        int ec  = (tid & 3) * 32;
        int node = node0 + row;
        if (node < NN) {
            if (ec < OC) {
                __half* tp = g_th + (size_t)node * OC + ec;
                float*  zp = g_aggF + (size_t)node * OC + ec;
#pragma unroll
                for (int q = 0; q < 4; q++) {
                    const float* sp = Df + row * FLD + ec + q * 8;
                    uint4 o;
                    o.x = h2u(__floats2half2_rn(sp[0], sp[1]));
                    o.y = h2u(__floats2half2_rn(sp[2], sp[3]));
                    o.z = h2u(__floats2half2_rn(sp[4], sp[5]));
                    o.w = h2u(__floats2half2_rn(sp[6], sp[7]));
                    *reinterpret_cast<uint4*>(tp + q * 8) = o;
                }
#pragma unroll
                for (int q = 0; q < 8; q++)
                    *reinterpret_cast<float4*>(zp + q * 4) =
                        make_float4(0.f, 0.f, 0.f, 0.f);
            } else {
                float* pp = g_po + (size_t)node * OC + (ec - OC);
                float* zp = g_aggF + (size_t)node * OC + (ec - OC);
#pragma unroll
                for (int q = 0; q < 8; q++) {
                    *reinterpret_cast<float4*>(pp + q * 4) =
                        *reinterpret_cast<const float4*>(Df + row * FLD + ec + q * 4);
                    *reinterpret_cast<float4*>(zp + q * 4) =
                        make_float4(0.f, 0.f, 0.f, 0.f);
                }
            }
        }
    }
}

// ---------------- kernel 4: scatter th, quarter-warp per edge, MLP-4 --------
__global__ void k_scatter_t(const int* __restrict__ ei) {
    int gw = (blockIdx.x * blockDim.x + threadIdx.x) >> 5;
    int lane = threadIdx.x & 31;
    int sub = lane >> 3;     // quarter-warp
    int sl  = lane & 7;      // covers 8 halves (16B) of the 64-col row
    int e0 = (gw * 4 + sub) * 4;
    if (e0 >= NE) return;
    int s[4], d[4];
    bool ok[4];
#pragma unroll
    for (int e = 0; e < 4; e++) {
        s[e] = ei[e0 + e];
        d[e] = ei[NE + e0 + e];
        ok[e] = ((unsigned)s[e] < NN) && ((unsigned)d[e] < NN);
    }
    uint4 hv[4];
#pragma unroll
    for (int e = 0; e < 4; e++)
        if (ok[e])
            hv[e] = *reinterpret_cast<const uint4*>(g_th + (size_t)s[e] * OC + sl * 8);
#pragma unroll
    for (int e = 0; e < 4; e++)
        if (ok[e]) {
            float2 f0 = __half22float2(*reinterpret_cast<__half2*>(&hv[e].x));
            float2 f1 = __half22float2(*reinterpret_cast<__half2*>(&hv[e].y));
            float2 f2 = __half22float2(*reinterpret_cast<__half2*>(&hv[e].z));
            float2 f3 = __half22float2(*reinterpret_cast<__half2*>(&hv[e].w));
            float* a = g_aggF + (size_t)d[e] * OC + sl * 8;
            red_add_v4(a,     make_float4(f0.x, f0.y, f1.x, f1.y));
            red_add_v4(a + 4, make_float4(f2.x, f2.y, f3.x, f3.y));
        }
}

// ---------------- kernel 5: out = aggF / max(cnt0,1) + po -------------------
__global__ void k_final(float* __restrict__ out) {
    int i = blockIdx.x * blockDim.x + threadIdx.x;
    int stride = gridDim.x * blockDim.x;
    int n4 = NN * OC / 4;
    const float4* a4 = reinterpret_cast<const float4*>(g_aggF);
    const float4* p4 = reinterpret_cast<const float4*>(g_po);
    float4* o4 = reinterpret_cast<float4*>(out);
    for (int j = i; j < n4; j += stride) {
        int node = j / (OC / 4);
        float inv = 1.f / fmaxf(g_cnt[node], 1.f);
        float4 a = a4[j];
        float4 p = p4[j];
        o4[j] = make_float4(a.x * inv + p.x, a.y * inv + p.y,
                            a.z * inv + p.z, a.w * inv + p.w);
    }
}

// ---------------- launch ----------------------------------------------------
extern "C" void kernel_launch(void* const* d_in, const int* in_sizes, int n_in,
                              void* d_out, int out_size) {
    const float* x   = (const float*)d_in[0];
    const float* Wl  = (const float*)d_in[1];
    const float* bl  = (const float*)d_in[2];
    const float* Wr  = (const float*)d_in[3];
    const float* Wlf = (const float*)d_in[4];
    const float* blf = (const float*)d_in[5];
    const float* Wrf = (const float*)d_in[6];
    const int* ei0   = (const int*)d_in[7];
    const int* ei1   = (const int*)d_in[8];
    const int* ei2   = (const int*)d_in[9];
    float* out = (float*)d_out;

    void *pagg, *pcnt;
    cudaGetSymbolAddress(&pagg, g_agg);
    cudaGetSymbolAddress(&pcnt, g_cnt);
    cudaMemsetAsync(pagg, 0, (size_t)NREL * NN * C * sizeof(float), 0);
    cudaMemsetAsync(pcnt, 0, (size_t)NREL * NN * sizeof(float), 0);

    k_prep<<<64, 256>>>(Wl, Wr, Wlf, Wrf, bl, blf);
    k_xh<<<1024, 256>>>(x);

    // half-warp per edge, MLP-4: 8 edges/warp, 8 warps/block
    dim3 sgrid((NE / 8 + 7) / 8, 3);
    k_scatter_x<<<sgrid, 256>>>(ei0, ei1, ei2);

    const int SMEMF = 4 * 128 * HLD * 2;  // 139264
    cudaFuncSetAttribute(k_gemm_fused, cudaFuncAttributeMaxDynamicSharedMemorySize, SMEMF);
    int gb = (NN + 127) / 128;  // 782
    k_gemm_fused<<<gb, 512, SMEMF>>>();

    // quarter-warp per edge, MLP-4: 16 edges/warp, 8 warps/block
    k_scatter_t<<<(NE / 16 + 7) / 8, 256>>>(ei0);
    k_final<<<2048, 256>>>(out);
}

// round 11
// speedup vs baseline: 1.1732x; 1.1732x over previous
#include <cuda_runtime.h>
#include <cuda_fp16.h>
#include <mma.h>
#include <cstdint>

using namespace nvcuda;

#define NN 100000
#define NE 600000
#define C 128
#define OC 64
#define NREL 3
#define HLD 136   // fp16 tile stride (halves)
#define FLD 132   // f32 tile stride (floats)
#define TM 64     // nodes per CTA tile

// ---------------- scratch (static device globals) ---------------------------
__device__ float  g_agg[(size_t)NREL * NN * C];
__device__ float  g_cnt[NREL * NN];
__device__ __half g_xh[(size_t)NN * C];        // fp16 x (GEMM staging source)
__device__ float  g_t[(size_t)NN * OC];        // t (pre-aggregation, f32)
__device__ float  g_aggF[(size_t)NN * OC];
__device__ float  g_po[(size_t)NN * OC];
__device__ __half g_Whl[NREL * C * C];         // Wl fp16
__device__ __half g_Whr[NREL * C * C];         // Wr fp16
__device__ __half g_Whf[C * C];                // [Wlf | Wrf] fp16 [k][n]
__device__ float  g_bias_rep[NREL * 16 * C];   // bl replicated over 16 rows
__device__ float  g_bias_rep_f[16 * C];        // [0|blf] replicated over 16 rows

__device__ __forceinline__ uint32_t h2u(__half2 h) {
    return *reinterpret_cast<uint32_t*>(&h);
}
__device__ __forceinline__ void red_add_v4(float* p, float4 v) {
    asm volatile("red.global.add.v4.f32 [%0], {%1, %2, %3, %4};"
                 :: "l"(p), "f"(v.x), "f"(v.y), "f"(v.z), "f"(v.w) : "memory");
}
__device__ __forceinline__ uint32_t smem_u32(const void* p) {
    uint32_t a;
    asm("{ .reg .u64 t; cvta.to.shared.u64 t, %1; cvt.u32.u64 %0, t; }"
        : "=r"(a) : "l"(p));
    return a;
}
__device__ __forceinline__ void cpa16(uint32_t dst, const void* src) {
    asm volatile("cp.async.ca.shared.global [%0], [%1], 16;"
                 :: "r"(dst), "l"(src) : "memory");
}
__device__ __forceinline__ void cpa16z(uint32_t dst, const void* src, bool ok) {
    int sz = ok ? 16 : 0;
    asm volatile("cp.async.ca.shared.global [%0], [%1], 16, %2;"
                 :: "r"(dst), "l"(src), "r"(sz) : "memory");
}
#define CPA_COMMIT() asm volatile("cp.async.commit_group;" ::: "memory")
#define CPA_WAIT0()  asm volatile("cp.async.wait_group 0;" ::: "memory")

// ---------------- kernel P: biases + fp16 weights ---------------------------
__global__ void k_prep(const float* __restrict__ Wl, const float* __restrict__ Wr,
                       const float* __restrict__ Wlf, const float* __restrict__ Wrf,
                       const float* __restrict__ bl, const float* __restrict__ blf) {
    int i0 = blockIdx.x * blockDim.x + threadIdx.x;
    int stride = gridDim.x * blockDim.x;
    for (int i = i0; i < NREL * C * C; i += stride) {
        g_Whl[i] = __float2half(Wl[i]);
        g_Whr[i] = __float2half(Wr[i]);
    }
    for (int i = i0; i < C * C; i += stride) {
        int n = i & (C - 1), k = i >> 7;
        float v = (n < OC) ? Wlf[k * OC + n] : Wrf[k * OC + (n - OC)];
        g_Whf[i] = __float2half(v);
    }
    for (int i = i0; i < NREL * 16 * C; i += stride) {
        int r = i / (16 * C);
        int col = i & (C - 1);
        g_bias_rep[i] = bl[r * C + col];
    }
    for (int i = i0; i < 16 * C; i += stride) {
        int col = i & (C - 1);
        g_bias_rep_f[i] = (col < OC) ? 0.f : blf[col - OC];
    }
}

// ---------------- kernel X: x -> fp16 (GEMM staging source) -----------------
__global__ void k_xh(const float* __restrict__ x) {
    int i0 = blockIdx.x * blockDim.x + threadIdx.x;
    int stride = gridDim.x * blockDim.x;
    int n8 = NN * C / 8;
    for (int i = i0; i < n8; i += stride) {
        float4 a = *reinterpret_cast<const float4*>(x + (size_t)i * 8);
        float4 b = *reinterpret_cast<const float4*>(x + (size_t)i * 8 + 4);
        uint4 o;
        o.x = h2u(__floats2half2_rn(a.x, a.y));
        o.y = h2u(__floats2half2_rn(a.z, a.w));
        o.z = h2u(__floats2half2_rn(b.x, b.y));
        o.w = h2u(__floats2half2_rn(b.z, b.w));
        *reinterpret_cast<uint4*>(g_xh + (size_t)i * 8) = o;
    }
}

// ---------------- kernel 1: scatter x, 4 edges per warp (R8 measured) -------
__global__ void k_scatter_x(const float* __restrict__ x,
                            const int* __restrict__ ei0,
                            const int* __restrict__ ei1,
                            const int* __restrict__ ei2) {
    int r = blockIdx.y;
    const int* ei = (r == 0) ? ei0 : (r == 1) ? ei1 : ei2;
    int w = (blockIdx.x * blockDim.x + threadIdx.x) >> 5;
    int lane = threadIdx.x & 31;
    int e0 = w * 4;
    if (e0 >= NE) return;
    int s[4], d[4];
    bool ok[4];
#pragma unroll
    for (int e = 0; e < 4; e++) {
        s[e] = ei[e0 + e];
        d[e] = ei[NE + e0 + e];
        ok[e] = ((unsigned)s[e] < NN) && ((unsigned)d[e] < NN);
    }
    float4 v[4];
#pragma unroll
    for (int e = 0; e < 4; e++)
        if (ok[e])
            v[e] = *reinterpret_cast<const float4*>(x + (size_t)s[e] * C + lane * 4);
#pragma unroll
    for (int e = 0; e < 4; e++)
        if (ok[e])
            red_add_v4(g_agg + (size_t)r * NN * C + (size_t)d[e] * C + lane * 4, v[e]);
    if (lane < 4 && ok[lane])
        atomicAdd(&g_cnt[r * NN + d[lane]], 1.f);
}

// ---------------- fused fp16 WMMA GEMM kernel -------------------------------
// 64-node tiles, 256 threads (8 warps, 2x4 of 32x32), 2 CTAs/SM for overlap.
__global__ __launch_bounds__(256, 2)
void k_gemm_fused() {
    extern __shared__ char smraw[];
    __half* X_s  = reinterpret_cast<__half*>(smraw);             // [64][HLD]
    __half* A_s  = X_s + TM * HLD;                               // [64][HLD]
    __half* Wl_s = A_s + TM * HLD;                               // [128][HLD]
    __half* Wr_s = Wl_s + 128 * HLD;                             // [128][HLD]
    float*  H32  = reinterpret_cast<float*>(smraw);              // [64][FLD] over X+A
    __half* Hh   = Wl_s;                                         // [64][HLD] over Wl
    __half* Wf_s = Wr_s;                                         // [128][HLD] over Wr
    float*  Df   = reinterpret_cast<float*>(smraw);              // [64][FLD] over X+A

    uint32_t base = smem_u32(smraw);
    uint32_t xa  = base;
    uint32_t wla = base + 2 * TM * HLD * 2;
    uint32_t wra = wla + 128 * HLD * 2;

    int tid  = threadIdx.x;
    int wid  = tid >> 5;
    int node0 = blockIdx.x * TM;
    int wm = (wid >> 2) * 32;
    int wn = (wid & 3) * 32;

    // X tile via cp.async from g_xh (zero-fill OOB rows)
    for (int it = tid; it < TM * 16; it += 256) {
        int row = it >> 4, c = it & 15;
        int node = node0 + row;
        bool ok = node < NN;
        const __half* src = g_xh + (size_t)(ok ? node : 0) * C + c * 8;
        cpa16z(xa + row * (HLD * 2) + c * 16, src, ok);
    }

    wmma::fragment<wmma::accumulator, 16, 16, 16, float> hfrag[2][2];
#pragma unroll
    for (int i = 0; i < 2; i++)
#pragma unroll
        for (int j = 0; j < 2; j++) wmma::fill_fragment(hfrag[i][j], 0.f);
    const float inv3 = 1.f / 3.f;

    for (int r = 0; r < NREL; r++) {
        __syncthreads();  // prev MMAs done reading A_s/W tiles
        // W tiles via cp.async (fp16 pre-converted)
        {
            const __half* wl = g_Whl + (size_t)r * C * C;
            const __half* wr = g_Whr + (size_t)r * C * C;
            for (int it = tid; it < 128 * 16; it += 256) {
                int kk = it >> 4, c = it & 15;
                cpa16(wla + kk * (HLD * 2) + c * 16, wl + kk * C + c * 8);
                cpa16(wra + kk * (HLD * 2) + c * 16, wr + kk * C + c * 8);
            }
            CPA_COMMIT();
        }
        // A tile: sync f32 loads + convert (atomic-written source must be f32)
        {
            const float* aggr = g_agg + (size_t)r * NN * C;
            const float* cntr = g_cnt + r * NN;
            for (int it = tid; it < TM * 32; it += 256) {
                int row = it >> 5, c4 = it & 31;
                int node = node0 + row;
                float4 v = make_float4(0.f, 0.f, 0.f, 0.f);
                if (node < NN) {
                    float inv = 1.f / fmaxf(cntr[node], 1.f);
                    float4 a = *reinterpret_cast<const float4*>(
                        aggr + (size_t)node * C + c4 * 4);
                    v.x = a.x * inv; v.y = a.y * inv;
                    v.z = a.z * inv; v.w = a.w * inv;
                }
                __half2* dp = reinterpret_cast<__half2*>(A_s + row * HLD + c4 * 4);
                dp[0] = __floats2half2_rn(v.x, v.y);
                dp[1] = __floats2half2_rn(v.z, v.w);
            }
        }

        wmma::fragment<wmma::accumulator, 16, 16, 16, float> acc[2][2];
#pragma unroll
        for (int i = 0; i < 2; i++)
#pragma unroll
            for (int j = 0; j < 2; j++)
                wmma::load_matrix_sync(acc[i][j],
                    g_bias_rep + r * 16 * C + wn + j * 16, C, wmma::mem_row_major);

        CPA_WAIT0();
        __syncthreads();

#pragma unroll
        for (int ks = 0; ks < 8; ks++) {
            int k = ks * 16;
            wmma::fragment<wmma::matrix_a, 16, 16, 16, __half,
                           wmma::row_major> af[2], xf[2];
            wmma::fragment<wmma::matrix_b, 16, 16, 16, __half,
                           wmma::row_major> lf[2], rf[2];
#pragma unroll
            for (int i = 0; i < 2; i++) {
                wmma::load_matrix_sync(af[i], A_s + (wm + i * 16) * HLD + k, HLD);
                wmma::load_matrix_sync(xf[i], X_s + (wm + i * 16) * HLD + k, HLD);
            }
#pragma unroll
            for (int j = 0; j < 2; j++) {
                wmma::load_matrix_sync(lf[j], Wl_s + k * HLD + wn + j * 16, HLD);
                wmma::load_matrix_sync(rf[j], Wr_s + k * HLD + wn + j * 16, HLD);
            }
#pragma unroll
            for (int i = 0; i < 2; i++)
#pragma unroll
                for (int j = 0; j < 2; j++) {
                    wmma::mma_sync(acc[i][j], af[i], lf[j], acc[i][j]);
                    wmma::mma_sync(acc[i][j], xf[i], rf[j], acc[i][j]);
                }
        }

#pragma unroll
        for (int i = 0; i < 2; i++)
#pragma unroll
            for (int j = 0; j < 2; j++)
#pragma unroll
                for (int t = 0; t < hfrag[i][j].num_elements; t++)
                    hfrag[i][j].x[t] += fmaxf(acc[i][j].x[t], 0.f) * inv3;
    }

    // ---------------- final GEMM: D_f = h @ [Wlf | Wrf] ---------------------
    __syncthreads();  // MMAs done reading X_s/A_s/W
#pragma unroll
    for (int i = 0; i < 2; i++)
#pragma unroll
        for (int j = 0; j < 2; j++)
            wmma::store_matrix_sync(H32 + (wm + i * 16) * FLD + wn + j * 16,
                                    hfrag[i][j], FLD, wmma::mem_row_major);
    __syncthreads();
    // Wf via cp.async (over Wr_s); convert H32 -> Hh (over Wl_s)
    for (int it = tid; it < 128 * 16; it += 256) {
        int kk = it >> 4, c = it & 15;
        cpa16(wra + kk * (HLD * 2) + c * 16, g_Whf + kk * C + c * 8);
    }
    CPA_COMMIT();
    for (int it = tid; it < TM * 64; it += 256) {
        int row = it >> 6, c2 = it & 63;
        float2 v = *reinterpret_cast<const float2*>(H32 + row * FLD + c2 * 2);
        *reinterpret_cast<__half2*>(Hh + row * HLD + c2 * 2) =
            __floats2half2_rn(v.x, v.y);
    }
    CPA_WAIT0();
    __syncthreads();

    {
        wmma::fragment<wmma::accumulator, 16, 16, 16, float> acc2[2][2];
#pragma unroll
        for (int i = 0; i < 2; i++)
#pragma unroll
            for (int j = 0; j < 2; j++)
                wmma::load_matrix_sync(acc2[i][j],
                    g_bias_rep_f + wn + j * 16, C, wmma::mem_row_major);

#pragma unroll
        for (int ks = 0; ks < 8; ks++) {
            int k = ks * 16;
            wmma::fragment<wmma::matrix_a, 16, 16, 16, __half,
                           wmma::row_major> hf[2];
            wmma::fragment<wmma::matrix_b, 16, 16, 16, __half,
                           wmma::row_major> wf[2];
#pragma unroll
            for (int i = 0; i < 2; i++)
                wmma::load_matrix_sync(hf[i], Hh + (wm + i * 16) * HLD + k, HLD);
#pragma unroll
            for (int j = 0; j < 2; j++)
                wmma::load_matrix_sync(wf[j], Wf_s + k * HLD + wn + j * 16, HLD);
#pragma unroll
            for (int i = 0; i < 2; i++)
#pragma unroll
                for (int j = 0; j < 2; j++)
                    wmma::mma_sync(acc2[i][j], hf[i], wf[j], acc2[i][j]);
        }
        __syncthreads();  // all warps done reading Hh/Wf (and H32 region)
#pragma unroll
        for (int i = 0; i < 2; i++)
#pragma unroll
            for (int j = 0; j < 2; j++)
                wmma::store_matrix_sync(Df + (wm + i * 16) * FLD + wn + j * 16,
                                        acc2[i][j], FLD, wmma::mem_row_major);
        __syncthreads();
    }

    // epilogue: t (cols 0..63), po (cols 64..127); zero this tile's aggF slice
    {
        int row = tid >> 2;
        int ec  = (tid & 3) * 32;
        int node = node0 + row;
        if (node < NN) {
            if (ec < OC) {
                float* tp = g_t + (size_t)node * OC + ec;
                float* zp = g_aggF + (size_t)node * OC + ec;
#pragma unroll
                for (int q = 0; q < 8; q++) {
                    *reinterpret_cast<float4*>(tp + q * 4) =
                        *reinterpret_cast<const float4*>(Df + row * FLD + ec + q * 4);
                    *reinterpret_cast<float4*>(zp + q * 4) =
                        make_float4(0.f, 0.f, 0.f, 0.f);
                }
            } else {
                float* pp = g_po + (size_t)node * OC + (ec - OC);
                float* zp = g_aggF + (size_t)node * OC + (ec - OC);
#pragma unroll
                for (int q = 0; q < 8; q++) {
                    *reinterpret_cast<float4*>(pp + q * 4) =
                        *reinterpret_cast<const float4*>(Df + row * FLD + ec + q * 4);
                    *reinterpret_cast<float4*>(zp + q * 4) =
                        make_float4(0.f, 0.f, 0.f, 0.f);
                }
            }
        }
    }
}

// ---------------- kernel 4: scatter t, 4 edges per half-warp (R8 measured) --
__global__ void k_scatter_t(const int* __restrict__ ei) {
    int hw = (blockIdx.x * blockDim.x + threadIdx.x) >> 4;
    int lane = threadIdx.x & 15;
    int e0 = hw * 4;
    if (e0 >= NE) return;
    int s[4], d[4];
    bool ok[4];
#pragma unroll
    for (int e = 0; e < 4; e++) {
        s[e] = ei[e0 + e];
        d[e] = ei[NE + e0 + e];
        ok[e] = ((unsigned)s[e] < NN) && ((unsigned)d[e] < NN);
    }
    float4 v[4];
#pragma unroll
    for (int e = 0; e < 4; e++)
        if (ok[e])
            v[e] = *reinterpret_cast<const float4*>(g_t + (size_t)s[e] * OC + lane * 4);
#pragma unroll
    for (int e = 0; e < 4; e++)
        if (ok[e])
            red_add_v4(g_aggF + (size_t)d[e] * OC + lane * 4, v[e]);
}

// ---------------- kernel 5: out = aggF / max(cnt0,1) + po -------------------
__global__ void k_final(float* __restrict__ out) {
    int i = blockIdx.x * blockDim.x + threadIdx.x;
    int stride = gridDim.x * blockDim.x;
    int n4 = NN * OC / 4;
    const float4* a4 = reinterpret_cast<const float4*>(g_aggF);
    const float4* p4 = reinterpret_cast<const float4*>(g_po);
    float4* o4 = reinterpret_cast<float4*>(out);
    for (int j = i; j < n4; j += stride) {
        int node = j / (OC / 4);
        float inv = 1.f / fmaxf(g_cnt[node], 1.f);
        float4 a = a4[j];
        float4 p = p4[j];
        o4[j] = make_float4(a.x * inv + p.x, a.y * inv + p.y,
                            a.z * inv + p.z, a.w * inv + p.w);
    }
}

// ---------------- launch ----------------------------------------------------
extern "C" void kernel_launch(void* const* d_in, const int* in_sizes, int n_in,
                              void* d_out, int out_size) {
    const float* x   = (const float*)d_in[0];
    const float* Wl  = (const float*)d_in[1];
    const float* bl  = (const float*)d_in[2];
    const float* Wr  = (const float*)d_in[3];
    const float* Wlf = (const float*)d_in[4];
    const float* blf = (const float*)d_in[5];
    const float* Wrf = (const float*)d_in[6];
    const int* ei0   = (const int*)d_in[7];
    const int* ei1   = (const int*)d_in[8];
    const int* ei2   = (const int*)d_in[9];
    float* out = (float*)d_out;

    void *pagg, *pcnt;
    cudaGetSymbolAddress(&pagg, g_agg);
    cudaGetSymbolAddress(&pcnt, g_cnt);
    cudaMemsetAsync(pagg, 0, (size_t)NREL * NN * C * sizeof(float), 0);
    cudaMemsetAsync(pcnt, 0, (size_t)NREL * NN * sizeof(float), 0);

    k_prep<<<64, 256>>>(Wl, Wr, Wlf, Wrf, bl, blf);
    k_xh<<<1024, 256>>>(x);

    // 4 edges per warp, 8 warps per 256-thr block, y = relation (R8 config)
    dim3 sgrid((NE / 4 + 7) / 8, 3);
    k_scatter_x<<<sgrid, 256>>>(x, ei0, ei1, ei2);

    const int SMEMF = (2 * TM + 2 * 128) * HLD * 2;  // 104448
    cudaFuncSetAttribute(k_gemm_fused, cudaFuncAttributeMaxDynamicSharedMemorySize, SMEMF);
    int gb = (NN + TM - 1) / TM;  // 1563
    k_gemm_fused<<<gb, 256, SMEMF>>>();

    // 4 edges per half-warp, 16 half-warps per 256-thr block (R8 config)
    k_scatter_t<<<(NE / 4 + 15) / 16, 256>>>(ei0);
    k_final<<<2048, 256>>>(out);
}

// round 12
// speedup vs baseline: 1.2947x; 1.1035x over previous
#include <cuda_runtime.h>
#include <cuda_fp16.h>
#include <mma.h>
#include <cstdint>

using namespace nvcuda;

#define NN 100000
#define NE 600000
#define C 128
#define OC 64
#define NREL 3
#define HLD 136    // fp16 tile stride (halves) -> 272B rows
#define FLD 132    // f32 tile stride (floats)
#define TM 64      // nodes per CTA tile
#define WHB 17408  // bytes of one 64-row fp16 half-matrix [64][HLD]

// ---------------- scratch (static device globals) ---------------------------
__device__ float  g_agg[(size_t)NREL * NN * C];
__device__ float  g_cnt[NREL * NN];
__device__ __half g_xh[(size_t)NN * C];        // fp16 x (GEMM staging source)
__device__ float  g_t[(size_t)NN * OC];        // t (pre-aggregation, f32)
__device__ float  g_aggF[(size_t)NN * OC];
__device__ float  g_po[(size_t)NN * OC];
__device__ __half g_Whl[NREL * C * C];         // Wl fp16
__device__ __half g_Whr[NREL * C * C];         // Wr fp16
__device__ __half g_Whf[C * C];                // [Wlf | Wrf] fp16 [k][n]
__device__ float  g_iota[16 * 16];             // iota[r][c] = c (fragment col map)

__device__ __forceinline__ uint32_t h2u(__half2 h) {
    return *reinterpret_cast<uint32_t*>(&h);
}
__device__ __forceinline__ void red_add_v4(float* p, float4 v) {
    asm volatile("red.global.add.v4.f32 [%0], {%1, %2, %3, %4};"
                 :: "l"(p), "f"(v.x), "f"(v.y), "f"(v.z), "f"(v.w) : "memory");
}
__device__ __forceinline__ uint32_t smem_u32(const void* p) {
    uint32_t a;
    asm("{ .reg .u64 t; cvta.to.shared.u64 t, %1; cvt.u32.u64 %0, t; }"
        : "=r"(a) : "l"(p));
    return a;
}
__device__ __forceinline__ void cpa16(uint32_t dst, const void* src) {
    asm volatile("cp.async.ca.shared.global [%0], [%1], 16;"
                 :: "r"(dst), "l"(src) : "memory");
}
__device__ __forceinline__ void cpa16z(uint32_t dst, const void* src, bool ok) {
    int sz = ok ? 16 : 0;
    asm volatile("cp.async.ca.shared.global [%0], [%1], 16, %2;"
                 :: "r"(dst), "l"(src), "r"(sz) : "memory");
}
#define CPA_COMMIT() asm volatile("cp.async.commit_group;" ::: "memory")
#define CPA_WAIT0()  asm volatile("cp.async.wait_group 0;" ::: "memory")
#define CPA_WAIT1()  asm volatile("cp.async.wait_group 1;" ::: "memory")

// ---------------- kernel P: fp16 weights + iota -----------------------------
__global__ void k_prep(const float* __restrict__ Wl, const float* __restrict__ Wr,
                       const float* __restrict__ Wlf, const float* __restrict__ Wrf) {
    int i0 = blockIdx.x * blockDim.x + threadIdx.x;
    int stride = gridDim.x * blockDim.x;
    for (int i = i0; i < NREL * C * C; i += stride) {
        g_Whl[i] = __float2half(Wl[i]);
        g_Whr[i] = __float2half(Wr[i]);
    }
    for (int i = i0; i < C * C; i += stride) {
        int n = i & (C - 1), k = i >> 7;
        float v = (n < OC) ? Wlf[k * OC + n] : Wrf[k * OC + (n - OC)];
        g_Whf[i] = __float2half(v);
    }
    for (int i = i0; i < 256; i += stride)
        g_iota[i] = (float)(i & 15);
}

// ---------------- kernel X: x -> fp16 ---------------------------------------
__global__ void k_xh(const float* __restrict__ x) {
    int i0 = blockIdx.x * blockDim.x + threadIdx.x;
    int stride = gridDim.x * blockDim.x;
    int n8 = NN * C / 8;
    for (int i = i0; i < n8; i += stride) {
        float4 a = *reinterpret_cast<const float4*>(x + (size_t)i * 8);
        float4 b = *reinterpret_cast<const float4*>(x + (size_t)i * 8 + 4);
        uint4 o;
        o.x = h2u(__floats2half2_rn(a.x, a.y));
        o.y = h2u(__floats2half2_rn(a.z, a.w));
        o.z = h2u(__floats2half2_rn(b.x, b.y));
        o.w = h2u(__floats2half2_rn(b.z, b.w));
        *reinterpret_cast<uint4*>(g_xh + (size_t)i * 8) = o;
    }
}

// ---------------- kernel 1: scatter x, 4 edges per warp (R8 measured) -------
__global__ void k_scatter_x(const float* __restrict__ x,
                            const int* __restrict__ ei0,
                            const int* __restrict__ ei1,
                            const int* __restrict__ ei2) {
    int r = blockIdx.y;
    const int* ei = (r == 0) ? ei0 : (r == 1) ? ei1 : ei2;
    int w = (blockIdx.x * blockDim.x + threadIdx.x) >> 5;
    int lane = threadIdx.x & 31;
    int e0 = w * 4;
    if (e0 >= NE) return;
    int s[4], d[4];
    bool ok[4];
#pragma unroll
    for (int e = 0; e < 4; e++) {
        s[e] = ei[e0 + e];
        d[e] = ei[NE + e0 + e];
        ok[e] = ((unsigned)s[e] < NN) && ((unsigned)d[e] < NN);
    }
    float4 v[4];
#pragma unroll
    for (int e = 0; e < 4; e++)
        if (ok[e])
            v[e] = *reinterpret_cast<const float4*>(x + (size_t)s[e] * C + lane * 4);
#pragma unroll
    for (int e = 0; e < 4; e++)
        if (ok[e])
            red_add_v4(g_agg + (size_t)r * NN * C + (size_t)d[e] * C + lane * 4, v[e]);
    if (lane < 4 && ok[lane])
        atomicAdd(&g_cnt[r * NN + d[lane]], 1.f);
}

// ---------------- fused pipelined fp16 WMMA GEMM ----------------------------
// 64-node tiles, 256 thr (8 warps, 2x4 of 32x32), 2 CTAs/SM.
// 6-step pipeline (3 rel x 2 K-halves), W double-buffered via cp.async.
__global__ __launch_bounds__(256, 2)
void k_gemm_fused(const float* __restrict__ bl, const float* __restrict__ blf) {
    extern __shared__ char smraw[];
    __shared__ float bls[NREL * C + OC];                 // 1792B static
    __half* X_s = reinterpret_cast<__half*>(smraw);      // [64][HLD]
    __half* A_s = X_s + TM * HLD;                        // [64][HLD]
    // W buffers: buf(i) at 2*WHB + i*2*WHB ; Wl at +0, Wr at +WHB
    float*  H32 = reinterpret_cast<float*>(smraw);       // [64][FLD] over X+A
    float*  Df  = reinterpret_cast<float*>(smraw);       // [64][FLD] over X+A
    __half* WfS = reinterpret_cast<__half*>(smraw + 2 * WHB);      // over buf0 [128][HLD]
    __half* Hh  = reinterpret_cast<__half*>(smraw + 4 * WHB);      // over buf1 [64][HLD]

    uint32_t base = smem_u32(smraw);
    uint32_t xa = base;
    uint32_t wb0 = base + 2 * WHB;
    uint32_t wb1 = base + 4 * WHB;

    int tid = threadIdx.x;
    int wid = tid >> 5;
    int node0 = blockIdx.x * TM;
    int wm = (wid >> 2) * 32;
    int wn = (wid & 3) * 32;

    // biases -> smem
    for (int i = tid; i < NREL * C; i += 256) bls[i] = bl[i];
    if (tid < OC) bls[NREL * C + tid] = blf[tid];

    // prologue group G0: X tile + W(step 0 = rel0 half0) into buf0
    for (int it = tid; it < TM * 16; it += 256) {
        int row = it >> 4, c = it & 15;
        int node = node0 + row;
        bool ok = node < NN;
        cpa16z(xa + row * (HLD * 2) + c * 16,
               g_xh + (size_t)(ok ? node : 0) * C + c * 8, ok);
    }
    for (int it = tid; it < 64 * 16; it += 256) {
        int row = it >> 4, c = it & 15;
        cpa16(wb0 + row * (HLD * 2) + c * 16, g_Whl + row * C + c * 8);
        cpa16(wb0 + WHB + row * (HLD * 2) + c * 16, g_Whr + row * C + c * 8);
    }
    CPA_COMMIT();  // G0

    // iota fragment (col-within-16-tile per accumulator element)
    wmma::fragment<wmma::accumulator, 16, 16, 16, float> iotaf;
    wmma::load_matrix_sync(iotaf, g_iota, 16, wmma::mem_row_major);

    wmma::fragment<wmma::accumulator, 16, 16, 16, float> hfrag[2][2];
#pragma unroll
    for (int i = 0; i < 2; i++)
#pragma unroll
        for (int j = 0; j < 2; j++) wmma::fill_fragment(hfrag[i][j], 0.f);
    const float inv3 = 1.f / 3.f;

    wmma::fragment<wmma::accumulator, 16, 16, 16, float> acc[2][2];

    for (int s = 0; s < 6; s++) {
        int r = s >> 1, h = s & 1;
        uint32_t wcur = (s & 1) ? wb1 : wb0;
        __half* WlS = reinterpret_cast<__half*>(smraw + 2 * WHB + (s & 1) * 2 * WHB);
        __half* WrS = WlS + 64 * HLD;

        __syncthreads();  // all warps done with previous step's MMAs

        // prefetch next step's W into the other buffer
        if (s < 5) {
            int r2 = (s + 1) >> 1, h2 = (s + 1) & 1;
            const __half* wl = g_Whl + (size_t)r2 * C * C + h2 * 64 * C;
            const __half* wr = g_Whr + (size_t)r2 * C * C + h2 * 64 * C;
            uint32_t b = ((s + 1) & 1) ? wb1 : wb0;
            for (int it = tid; it < 64 * 16; it += 256) {
                int row = it >> 4, c = it & 15;
                cpa16(b + row * (HLD * 2) + c * 16, wl + row * C + c * 8);
                cpa16(b + WHB + row * (HLD * 2) + c * 16, wr + row * C + c * 8);
            }
        } else {
            // prefetch Wf (128 rows) into buf0 for the final GEMM
            for (int it = tid; it < 128 * 16; it += 256) {
                int row = it >> 4, c = it & 15;
                cpa16(wb0 + row * (HLD * 2) + c * 16, g_Whf + row * C + c * 8);
            }
        }
        CPA_COMMIT();

        if (h == 0) {
            // stage A tile for relation r (register-batched loads)
            const float* aggr = g_agg + (size_t)r * NN * C;
            const float* cntr = g_cnt + r * NN;
            float4 va[8];
            float  vc[8];
            bool   okr[8];
#pragma unroll
            for (int i = 0; i < 8; i++) {
                int idx = tid + i * 256;
                int row = idx >> 5, c4 = idx & 31;
                int node = node0 + row;
                okr[i] = node < NN;
                if (okr[i]) {
                    va[i] = *reinterpret_cast<const float4*>(
                        aggr + (size_t)node * C + c4 * 4);
                    vc[i] = cntr[node];
                }
            }
#pragma unroll
            for (int i = 0; i < 8; i++) {
                int idx = tid + i * 256;
                int row = idx >> 5, c4 = idx & 31;
                float4 v = make_float4(0.f, 0.f, 0.f, 0.f);
                if (okr[i]) {
                    float inv = 1.f / fmaxf(vc[i], 1.f);
                    v.x = va[i].x * inv; v.y = va[i].y * inv;
                    v.z = va[i].z * inv; v.w = va[i].w * inv;
                }
                __half2* dp = reinterpret_cast<__half2*>(A_s + row * HLD + c4 * 4);
                dp[0] = __floats2half2_rn(v.x, v.y);
                dp[1] = __floats2half2_rn(v.z, v.w);
            }
            // fresh accumulators for this relation (bias added at epilogue)
#pragma unroll
            for (int i = 0; i < 2; i++)
#pragma unroll
                for (int j = 0; j < 2; j++) wmma::fill_fragment(acc[i][j], 0.f);
        }

        CPA_WAIT1();      // current step's W group complete (next stays pending)
        __syncthreads();  // W + A visible to all warps

#pragma unroll
        for (int ks = 0; ks < 4; ks++) {
            int kloc = ks * 16;
            int kglb = h * 64 + kloc;
            wmma::fragment<wmma::matrix_a, 16, 16, 16, __half,
                           wmma::row_major> af[2], xf[2];
            wmma::fragment<wmma::matrix_b, 16, 16, 16, __half,
                           wmma::row_major> lf[2], rf[2];
#pragma unroll
            for (int i = 0; i < 2; i++) {
                wmma::load_matrix_sync(af[i], A_s + (wm + i * 16) * HLD + kglb, HLD);
                wmma::load_matrix_sync(xf[i], X_s + (wm + i * 16) * HLD + kglb, HLD);
            }
#pragma unroll
            for (int j = 0; j < 2; j++) {
                wmma::load_matrix_sync(lf[j], WlS + kloc * HLD + wn + j * 16, HLD);
                wmma::load_matrix_sync(rf[j], WrS + kloc * HLD + wn + j * 16, HLD);
            }
#pragma unroll
            for (int i = 0; i < 2; i++)
#pragma unroll
                for (int j = 0; j < 2; j++) {
                    wmma::mma_sync(acc[i][j], af[i], lf[j], acc[i][j]);
                    wmma::mma_sync(acc[i][j], xf[i], rf[j], acc[i][j]);
                }
        }

        if (h == 1) {
            // h += relu(acc + bias)/3 ; bias column via iota fragment
#pragma unroll
            for (int i = 0; i < 2; i++)
#pragma unroll
                for (int j = 0; j < 2; j++)
#pragma unroll
                    for (int t = 0; t < 8; t++) {
                        float b = bls[r * C + wn + j * 16 + (int)iotaf.x[t]];
                        hfrag[i][j].x[t] +=
                            fmaxf(acc[i][j].x[t] + b, 0.f) * inv3;
                    }
        }
    }

    // ---------------- final GEMM: D_f = h @ [Wlf | Wrf] ---------------------
    __syncthreads();  // all warps past step-5 MMAs (X/A/buf1 free)
#pragma unroll
    for (int i = 0; i < 2; i++)
#pragma unroll
        for (int j = 0; j < 2; j++)
            wmma::store_matrix_sync(H32 + (wm + i * 16) * FLD + wn + j * 16,
                                    hfrag[i][j], FLD, wmma::mem_row_major);
    __syncthreads();
    // convert H32 -> Hh (fp16, over buf1)
    for (int it = tid; it < TM * 64; it += 256) {
        int row = it >> 6, c2 = it & 63;
        float2 v = *reinterpret_cast<const float2*>(H32 + row * FLD + c2 * 2);
        *reinterpret_cast<__half2*>(Hh + row * HLD + c2 * 2) =
            __floats2half2_rn(v.x, v.y);
    }
    CPA_WAIT0();      // Wf (prefetched during step 5) in buf0
    __syncthreads();

    {
        wmma::fragment<wmma::accumulator, 16, 16, 16, float> acc2[2][2];
#pragma unroll
        for (int i = 0; i < 2; i++)
#pragma unroll
            for (int j = 0; j < 2; j++) wmma::fill_fragment(acc2[i][j], 0.f);

#pragma unroll
        for (int ks = 0; ks < 8; ks++) {
            int k = ks * 16;
            wmma::fragment<wmma::matrix_a, 16, 16, 16, __half,
                           wmma::row_major> hf[2];
            wmma::fragment<wmma::matrix_b, 16, 16, 16, __half,
                           wmma::row_major> wf[2];
#pragma unroll
            for (int i = 0; i < 2; i++)
                wmma::load_matrix_sync(hf[i], Hh + (wm + i * 16) * HLD + k, HLD);
#pragma unroll
            for (int j = 0; j < 2; j++)
                wmma::load_matrix_sync(wf[j], WfS + k * HLD + wn + j * 16, HLD);
#pragma unroll
            for (int i = 0; i < 2; i++)
#pragma unroll
                for (int j = 0; j < 2; j++)
                    wmma::mma_sync(acc2[i][j], hf[i], wf[j], acc2[i][j]);
        }
        __syncthreads();  // H32 region free for Df
#pragma unroll
        for (int i = 0; i < 2; i++)
#pragma unroll
            for (int j = 0; j < 2; j++)
                wmma::store_matrix_sync(Df + (wm + i * 16) * FLD + wn + j * 16,
                                        acc2[i][j], FLD, wmma::mem_row_major);
        __syncthreads();
    }

    // epilogue: t (cols 0..63), po (cols 64..127, +blf); zero aggF slice
    {
        int row = tid >> 2;
        int ec  = (tid & 3) * 32;
        int node = node0 + row;
        if (node < NN) {
            if (ec < OC) {
                float* tp = g_t + (size_t)node * OC + ec;
                float* zp = g_aggF + (size_t)node * OC + ec;
#pragma unroll
                for (int q = 0; q < 8; q++) {
                    *reinterpret_cast<float4*>(tp + q * 4) =
                        *reinterpret_cast<const float4*>(Df + row * FLD + ec + q * 4);
                    *reinterpret_cast<float4*>(zp + q * 4) =
                        make_float4(0.f, 0.f, 0.f, 0.f);
                }
            } else {
                float* pp = g_po + (size_t)node * OC + (ec - OC);
                float* zp = g_aggF + (size_t)node * OC + (ec - OC);
#pragma unroll
                for (int q = 0; q < 8; q++) {
                    float4 d = *reinterpret_cast<const float4*>(
                        Df + row * FLD + ec + q * 4);
                    const float* b = bls + NREL * C + (ec - OC) + q * 4;
                    *reinterpret_cast<float4*>(pp + q * 4) = make_float4(
                        d.x + b[0], d.y + b[1], d.z + b[2], d.w + b[3]);
                    *reinterpret_cast<float4*>(zp + q * 4) =
                        make_float4(0.f, 0.f, 0.f, 0.f);
                }
            }
        }
    }
}

// ---------------- kernel 4: scatter t, 4 edges per half-warp (R8 measured) --
__global__ void k_scatter_t(const int* __restrict__ ei) {
    int hw = (blockIdx.x * blockDim.x + threadIdx.x) >> 4;
    int lane = threadIdx.x & 15;
    int e0 = hw * 4;
    if (e0 >= NE) return;
    int s[4], d[4];
    bool ok[4];
#pragma unroll
    for (int e = 0; e < 4; e++) {
        s[e] = ei[e0 + e];
        d[e] = ei[NE + e0 + e];
        ok[e] = ((unsigned)s[e] < NN) && ((unsigned)d[e] < NN);
    }
    float4 v[4];
#pragma unroll
    for (int e = 0; e < 4; e++)
        if (ok[e])
            v[e] = *reinterpret_cast<const float4*>(g_t + (size_t)s[e] * OC + lane * 4);
#pragma unroll
    for (int e = 0; e < 4; e++)
        if (ok[e])
            red_add_v4(g_aggF + (size_t)d[e] * OC + lane * 4, v[e]);
}

// ---------------- kernel 5: out = aggF / max(cnt0,1) + po -------------------
__global__ void k_final(float* __restrict__ out) {
    int i = blockIdx.x * blockDim.x + threadIdx.x;
    int stride = gridDim.x * blockDim.x;
    int n4 = NN * OC / 4;
    const float4* a4 = reinterpret_cast<const float4*>(g_aggF);
    const float4* p4 = reinterpret_cast<const float4*>(g_po);
    float4* o4 = reinterpret_cast<float4*>(out);
    for (int j = i; j < n4; j += stride) {
        int node = j / (OC / 4);
        float inv = 1.f / fmaxf(g_cnt[node], 1.f);
        float4 a = a4[j];
        float4 p = p4[j];
        o4[j] = make_float4(a.x * inv + p.x, a.y * inv + p.y,
                            a.z * inv + p.z, a.w * inv + p.w);
    }
}

// ---------------- launch ----------------------------------------------------
extern "C" void kernel_launch(void* const* d_in, const int* in_sizes, int n_in,
                              void* d_out, int out_size) {
    const float* x   = (const float*)d_in[0];
    const float* Wl  = (const float*)d_in[1];
    const float* bl  = (const float*)d_in[2];
    const float* Wr  = (const float*)d_in[3];
    const float* Wlf = (const float*)d_in[4];
    const float* blf = (const float*)d_in[5];
    const float* Wrf = (const float*)d_in[6];
    const int* ei0   = (const int*)d_in[7];
    const int* ei1   = (const int*)d_in[8];
    const int* ei2   = (const int*)d_in[9];
    float* out = (float*)d_out;

    void *pagg, *pcnt;
    cudaGetSymbolAddress(&pagg, g_agg);
    cudaGetSymbolAddress(&pcnt, g_cnt);
    cudaMemsetAsync(pagg, 0, (size_t)NREL * NN * C * sizeof(float), 0);
    cudaMemsetAsync(pcnt, 0, (size_t)NREL * NN * sizeof(float), 0);

    k_prep<<<64, 256>>>(Wl, Wr, Wlf, Wrf);
    k_xh<<<1024, 256>>>(x);

    // 4 edges per warp, 8 warps per 256-thr block, y = relation (R8 config)
    dim3 sgrid((NE / 4 + 7) / 8, 3);
    k_scatter_x<<<sgrid, 256>>>(x, ei0, ei1, ei2);

    const int SMEMF = 6 * WHB;  // X + A + 2 W half-buffers = 104448
    cudaFuncSetAttribute(k_gemm_fused, cudaFuncAttributeMaxDynamicSharedMemorySize, SMEMF);
    int gb = (NN + TM - 1) / TM;  // 1563
    k_gemm_fused<<<gb, 256, SMEMF>>>(bl, blf);

    // 4 edges per half-warp, 16 half-warps per 256-thr block (R8 config)
    k_scatter_t<<<(NE / 4 + 15) / 16, 256>>>(ei0);
    k_final<<<2048, 256>>>(out);
}